// round 14
// baseline (speedup 1.0000x reference)
#include <cuda_runtime.h>
#include <cuda_bf16.h>

#define NN 50000
#define NE 800000
#define D  64
#define WPAD 68
#define NBLK 64                  // nodes per GEMM block (2 per thread)
#define GEMM_BLOCKS ((NN + NBLK - 1) / NBLK)   // 782
#define SCAN_BLOCKS 196          // 196*256 = 50176 >= NN; 196 = 28*7

typedef unsigned long long ull;

// Packed fp32 FMA (Blackwell f32x2): 2 MACs per issue, only reachable via PTX.
#define FMA2(acc, a, b) \
    asm("fma.rn.f32x2 %0, %1, %2, %0;" : "+l"(acc) : "l"(a), "l"(b))
#define PACK2(out, f) do { \
    unsigned _u = __float_as_uint(f); \
    asm("mov.b64 %0, {%1, %2};" : "=l"(out) : "r"(_u), "r"(_u)); \
} while (0)
#define UNPACK2(lo, hi, v) do { \
    unsigned _a, _b; \
    asm("mov.b64 {%0, %1}, %2;" : "=r"(_a), "=r"(_b) : "l"(v)); \
    lo = __uint_as_float(_a); hi = __uint_as_float(_b); \
} while (0)

// Scratch (allocations forbidden; __device__ globals are the sanctioned path)
__device__ __align__(16) float g_msgs[NN * D];  // x @ Wm^T + bm
__device__ int g_counts[NN];                    // in-degree; zero-init (.bss) and
                                                // reset by scan1 each run
__device__ int g_offsets[NN + 1];               // CSR row offsets (exclusive scan)
__device__ int g_cursor[NN];                    // fill cursors for position scatter
__device__ int g_srcs[NE];                      // destination-grouped source ids
__device__ int g_bsums[SCAN_BLOCKS];            // per-block sums for grid scan

// ---------------------------------------------------------------------------
// Kernel 1: fused dual GEMM (f32x2 packed FMA) + degree histogram.
//   g_msgs = x @ Wm^T + bm   (feeds the gather)
//   out    = x @ Ws^T + bs   (self projection, straight to d_out)
// Thread = (2 nodes, 8 dims). Per k-step: 4x LDS.128 of W (as ulonglong2 ->
// register pairs usable directly as f32x2 operands, no repack), 2 x-loads +
// 2 packs, 16 FMA2 = 24 issues / 32 MACs (was 38/32 scalar FFMA).
// Histogram rides along as a grid-stride loop (REDG, no return). g_counts is
// zero on entry: .bss init first run, reset by scan1 every run (replay-safe).
// ---------------------------------------------------------------------------
__global__ __launch_bounds__(256) void dual_gemm_kernel(
    const float* __restrict__ x,
    const float* __restrict__ Wm, const float* __restrict__ bm,
    const float* __restrict__ Ws, const float* __restrict__ bs,
    const int*   __restrict__ ei,
    float* __restrict__ out)
{
    __shared__ float wm_sh[D * WPAD];
    __shared__ float ws_sh[D * WPAD];
    __shared__ float x_sh[NBLK * WPAD];

    const int t = threadIdx.x;
    const int nbase = blockIdx.x * NBLK;

    // Fused degree histogram: 782*256 = 200192 threads, 4 edges each.
    for (int e = blockIdx.x * 256 + t; e < NE; e += GEMM_BLOCKS * 256) {
        int c = __ldg(&ei[NE + e]);
        c = min(max(c, 0), NN - 1);
        atomicAdd(&g_counts[c], 1);
    }

    // Load both W matrices transposed: Wsh[k][d] = W[d][k]
    for (int i = t; i < D * D; i += 256) {
        int d = i >> 6;
        int k = i & 63;
        wm_sh[k * WPAD + d] = Wm[i];
        ws_sh[k * WPAD + d] = Ws[i];
    }
    // Load x tile (64 nodes x 64) via float4; clamp OOB rows (stores predicated)
    for (int v = t; v < NBLK * 16; v += 256) {
        int row = v >> 4;
        int c4  = (v & 15) * 4;
        int gnode = min(nbase + row, NN - 1);
        float4 xv = *reinterpret_cast<const float4*>(&x[gnode * D + c4]);
        *reinterpret_cast<float4*>(&x_sh[row * WPAD + c4]) = xv;
    }
    __syncthreads();

    const int g  = t >> 3;          // node pair 0..31 (2 nodes each)
    const int dq = (t & 7) * 8;     // output dim oct (16B-aligned: 272|k*272, 32|dq*4)

    // Accumulators: [node][dim-pair] as packed f32x2, zero-init (0ull == {0.f,0.f})
    ull am[2][4] = {{0,0,0,0},{0,0,0,0}};
    ull av[2][4] = {{0,0,0,0},{0,0,0,0}};

#pragma unroll
    for (int k = 0; k < D; ++k) {
        const ulonglong2* wmp = reinterpret_cast<const ulonglong2*>(&wm_sh[k * WPAD + dq]);
        const ulonglong2* wsp = reinterpret_cast<const ulonglong2*>(&ws_sh[k * WPAD + dq]);
        ulonglong2 wm0 = wmp[0], wm1 = wmp[1];   // dims dq..dq+3, dq+4..dq+7
        ulonglong2 ws0 = wsp[0], ws1 = wsp[1];
#pragma unroll
        for (int j = 0; j < 2; ++j) {
            float xv = x_sh[(g * 2 + j) * WPAD + k];
            ull xp; PACK2(xp, xv);
            FMA2(am[j][0], xp, wm0.x);
            FMA2(am[j][1], xp, wm0.y);
            FMA2(am[j][2], xp, wm1.x);
            FMA2(am[j][3], xp, wm1.y);
            FMA2(av[j][0], xp, ws0.x);
            FMA2(av[j][1], xp, ws0.y);
            FMA2(av[j][2], xp, ws1.x);
            FMA2(av[j][3], xp, ws1.y);
        }
    }

    // Epilogue: unpack, add bias, store 8 dims per node as two float4s.
    float bmv[8], bsv[8];
    *reinterpret_cast<float4*>(&bmv[0]) = *reinterpret_cast<const float4*>(&bm[dq]);
    *reinterpret_cast<float4*>(&bmv[4]) = *reinterpret_cast<const float4*>(&bm[dq + 4]);
    *reinterpret_cast<float4*>(&bsv[0]) = *reinterpret_cast<const float4*>(&bs[dq]);
    *reinterpret_cast<float4*>(&bsv[4]) = *reinterpret_cast<const float4*>(&bs[dq + 4]);

#pragma unroll
    for (int j = 0; j < 2; ++j) {
        int node = nbase + g * 2 + j;
        if (node < NN) {
            float ma[8], sa[8];
#pragma unroll
            for (int p = 0; p < 4; ++p) {
                UNPACK2(ma[2 * p], ma[2 * p + 1], am[j][p]);
                UNPACK2(sa[2 * p], sa[2 * p + 1], av[j][p]);
            }
#pragma unroll
            for (int i = 0; i < 8; ++i) { ma[i] += bmv[i]; sa[i] += bsv[i]; }
            const int o = node * D + dq;
            *reinterpret_cast<float4*>(&g_msgs[o])     = *reinterpret_cast<float4*>(&ma[0]);
            *reinterpret_cast<float4*>(&g_msgs[o + 4]) = *reinterpret_cast<float4*>(&ma[4]);
            *reinterpret_cast<float4*>(&out[o])        = *reinterpret_cast<float4*>(&sa[0]);
            *reinterpret_cast<float4*>(&out[o + 4])    = *reinterpret_cast<float4*>(&sa[4]);
        }
    }
}

// ---------------------------------------------------------------------------
// Grid scan (3 kernels).
// ---------------------------------------------------------------------------
__device__ __forceinline__ int warp_incl_scan(int v, int lane) {
#pragma unroll
    for (int off = 1; off < 32; off <<= 1) {
        int n = __shfl_up_sync(0xFFFFFFFFu, v, off);
        if (lane >= off) v += n;
    }
    return v;
}

// scan1: per-block exclusive scan of counts + RESET counts for next replay.
__global__ __launch_bounds__(256) void scan1_kernel() {
    __shared__ int wsum[8];
    const int t = threadIdx.x;
    const int lane = t & 31;
    const int w = t >> 5;
    const int idx = blockIdx.x * 256 + t;

    int v = 0;
    if (idx < NN) {
        v = g_counts[idx];
        g_counts[idx] = 0;          // reset for next graph replay
    }
    int inc = warp_incl_scan(v, lane);
    if (lane == 31) wsum[w] = inc;
    __syncthreads();

    if (w == 0) {
        int s = (lane < 8) ? wsum[lane] : 0;
        int si = warp_incl_scan(s, lane);
        if (lane < 8) wsum[lane] = si - s;   // exclusive warp offsets
        if (lane == 7) g_bsums[blockIdx.x] = si;
    }
    __syncthreads();

    if (idx < NN) g_offsets[idx] = inc - v + wsum[w];   // block-local exclusive
}

// scan2: one warp scans the 196 block sums, all loads upfront (1 L2 trip).
__global__ void scan2_kernel() {
    const int lane = threadIdx.x;   // 32 threads
    const int base = lane * 7;
    const bool act = (lane < 28);

    int v[7];
#pragma unroll
    for (int i = 0; i < 7; ++i) v[i] = act ? g_bsums[base + i] : 0;

    int s = 0;
#pragma unroll
    for (int i = 0; i < 7; ++i) s += v[i];

    int run = warp_incl_scan(s, lane) - s;   // exclusive prefix of this lane
#pragma unroll
    for (int i = 0; i < 7; ++i) {
        if (act) g_bsums[base + i] = run;
        run += v[i];
    }
    if (lane == 0) g_offsets[NN] = NE;   // every (clamped) edge is counted
}

// scan3: add block offsets, materialize offsets + fill cursors.
__global__ __launch_bounds__(256) void scan3_kernel() {
    const int idx = blockIdx.x * 256 + threadIdx.x;
    if (idx < NN) {
        int o = g_offsets[idx] + g_bsums[blockIdx.x];
        g_offsets[idx] = o;
        g_cursor[idx]  = o;
    }
}

// ---------------------------------------------------------------------------
// Position scatter: each edge claims a slot in its destination's CSR segment
// and records its SOURCE id there. 800k returning int atomics.
// ---------------------------------------------------------------------------
__global__ __launch_bounds__(256) void pos_kernel(const int* __restrict__ ei) {
    int e = blockIdx.x * 256 + threadIdx.x;
    if (e < NE) {
        int r = __ldg(&ei[e]);
        int c = __ldg(&ei[NE + e]);
        r = min(max(r, 0), NN - 1);
        c = min(max(c, 0), NN - 1);
        int p = atomicAdd(&g_cursor[c], 1);
        g_srcs[p] = r;
    }
}

// ---------------------------------------------------------------------------
// Warp-per-node gather + mean + self-add. ZERO atomics.
// Lane l owns dims {2l, 2l+1} via float2 (LDG.64). 4x edge unroll (avg deg 16).
// At the L2-read roofline (~205MB / 6300 B/cyc).
// ---------------------------------------------------------------------------
__global__ __launch_bounds__(256) void aggregate_kernel(float* __restrict__ out) {
    const int node = blockIdx.x * 8 + (threadIdx.x >> 5);
    if (node >= NN) return;
    const int lane = threadIdx.x & 31;

    const int start = __ldg(&g_offsets[node]);
    const int end   = __ldg(&g_offsets[node + 1]);

    const float2* __restrict__ msgs2 = reinterpret_cast<const float2*>(g_msgs);

    float ax = 0.f, ay = 0.f;
    int j = start;
    for (; j + 4 <= end; j += 4) {
        int s0 = __ldg(&g_srcs[j]);
        int s1 = __ldg(&g_srcs[j + 1]);
        int s2 = __ldg(&g_srcs[j + 2]);
        int s3 = __ldg(&g_srcs[j + 3]);
        float2 v0 = __ldg(&msgs2[s0 * 32 + lane]);
        float2 v1 = __ldg(&msgs2[s1 * 32 + lane]);
        float2 v2 = __ldg(&msgs2[s2 * 32 + lane]);
        float2 v3 = __ldg(&msgs2[s3 * 32 + lane]);
        ax += (v0.x + v1.x) + (v2.x + v3.x);
        ay += (v0.y + v1.y) + (v2.y + v3.y);
    }
    for (; j < end; ++j) {
        int s0 = __ldg(&g_srcs[j]);
        float2 v0 = __ldg(&msgs2[s0 * 32 + lane]);
        ax += v0.x;
        ay += v0.y;
    }

    const float inv = 1.0f / fmaxf((float)(end - start), 1.0f);
    float2* out2 = reinterpret_cast<float2*>(out);
    float2 o = out2[node * 32 + lane];
    o.x = fmaf(ax, inv, o.x);
    o.y = fmaf(ay, inv, o.y);
    out2[node * 32 + lane] = o;
}

// ---------------------------------------------------------------------------
// Serial single-stream launch (fork-join via side streams hung the container
// in R13; reverted). All launches on the capture/default stream.
// ---------------------------------------------------------------------------
extern "C" void kernel_launch(void* const* d_in, const int* in_sizes, int n_in,
                              void* d_out, int out_size)
{
    const float* x   = (const float*)d_in[0];
    const int*   ei  = (const int*)d_in[1];    // int32 (JAX x64-disabled)
    const float* Wm  = (const float*)d_in[2];
    const float* bm  = (const float*)d_in[3];
    const float* Ws  = (const float*)d_in[4];
    const float* bs  = (const float*)d_in[5];
    float*       out = (float*)d_out;

    (void)in_sizes; (void)n_in; (void)out_size;

    // 1) dual GEMM (f32x2 packed FMA) + fused degree histogram
    dual_gemm_kernel<<<GEMM_BLOCKS, 256>>>(x, Wm, bm, Ws, bs, ei, out);

    // 2) grid scan -> offsets + cursors (scan1 also resets g_counts)
    scan1_kernel<<<SCAN_BLOCKS, 256>>>();
    scan2_kernel<<<1, 32>>>();
    scan3_kernel<<<SCAN_BLOCKS, 256>>>();

    // 3) position scatter -> destination-grouped source list
    pos_kernel<<<(NE + 255) / 256, 256>>>(ei);

    // 4) gather + mean + self-add (atomic-free)
    aggregate_kernel<<<(NN + 7) / 8, 256>>>(out);
}

// round 15
// speedup vs baseline: 1.5143x; 1.5143x over previous
#include <cuda_runtime.h>
#include <cuda_bf16.h>

#define NN 50000
#define NE 800000
#define D  64
#define WPAD 68
#define NBLK 64                  // nodes per GEMM block (4 per thread)
#define GEMM_BLOCKS ((NN + NBLK - 1) / NBLK)   // 782
#define SCAN_BLOCKS 196          // 196*256 = 50176 >= NN; 196 = 28*7

// Scratch (allocations forbidden; __device__ globals are the sanctioned path)
__device__ __align__(16) float g_msgs[NN * D];  // x @ Wm^T + bm
__device__ int g_counts[NN];   // in-degree. Zero at entry every run: .bss on
                               // load, then DRAINED back to zero by pos_kernel
                               // (countdown slot claim) -> replay-safe.
__device__ int g_offsets[NN + 1];               // CSR row offsets (exclusive scan)
__device__ int g_srcs[NE];                      // destination-grouped source ids
__device__ int g_bsums[SCAN_BLOCKS];            // per-block sums for grid scan

// ---------------------------------------------------------------------------
// Kernel 1: fused dual GEMM (4-node register blocking, scalar FFMA — the
// f32x2 packed experiment regressed 72->107us and was reverted) + histogram.
//   g_msgs = x @ Wm^T + bm   (feeds the gather)
//   out    = x @ Ws^T + bs   (self projection, straight to d_out)
// At the fp32 FFMA roofline (~26us).
// ---------------------------------------------------------------------------
__global__ __launch_bounds__(256) void dual_gemm_kernel(
    const float* __restrict__ x,
    const float* __restrict__ Wm, const float* __restrict__ bm,
    const float* __restrict__ Ws, const float* __restrict__ bs,
    const int*   __restrict__ ei,
    float* __restrict__ out)
{
    __shared__ float wm_sh[D * WPAD];
    __shared__ float ws_sh[D * WPAD];
    __shared__ float x_sh[NBLK * WPAD];

    const int t = threadIdx.x;
    const int nbase = blockIdx.x * NBLK;

    // Fused degree histogram: 782*256 = 200192 threads, 4 edges each.
    for (int e = blockIdx.x * 256 + t; e < NE; e += GEMM_BLOCKS * 256) {
        int c = __ldg(&ei[NE + e]);
        c = min(max(c, 0), NN - 1);
        atomicAdd(&g_counts[c], 1);
    }

    // Load both W matrices transposed: Wsh[k][d] = W[d][k]
    for (int i = t; i < D * D; i += 256) {
        int d = i >> 6;
        int k = i & 63;
        wm_sh[k * WPAD + d] = Wm[i];
        ws_sh[k * WPAD + d] = Ws[i];
    }
    // Load x tile (64 nodes x 64) via float4; clamp OOB rows (stores predicated)
    for (int v = t; v < NBLK * 16; v += 256) {
        int row = v >> 4;
        int c4  = (v & 15) * 4;
        int gnode = min(nbase + row, NN - 1);
        float4 xv = *reinterpret_cast<const float4*>(&x[gnode * D + c4]);
        *reinterpret_cast<float4*>(&x_sh[row * WPAD + c4]) = xv;
    }
    __syncthreads();

    const int g  = t >> 4;          // node group 0..15 (4 nodes each)
    const int dq = (t & 15) * 4;    // output dim quad

    float4 am[4], av[4];
#pragma unroll
    for (int j = 0; j < 4; ++j) {
        am[j] = make_float4(0.f, 0.f, 0.f, 0.f);
        av[j] = make_float4(0.f, 0.f, 0.f, 0.f);
    }

#pragma unroll
    for (int k = 0; k < D; ++k) {
        float4 w1 = *reinterpret_cast<const float4*>(&wm_sh[k * WPAD + dq]);
        float4 w2 = *reinterpret_cast<const float4*>(&ws_sh[k * WPAD + dq]);
#pragma unroll
        for (int j = 0; j < 4; ++j) {
            float xv = x_sh[(g * 4 + j) * WPAD + k];
            am[j].x = fmaf(xv, w1.x, am[j].x);
            am[j].y = fmaf(xv, w1.y, am[j].y);
            am[j].z = fmaf(xv, w1.z, am[j].z);
            am[j].w = fmaf(xv, w1.w, am[j].w);
            av[j].x = fmaf(xv, w2.x, av[j].x);
            av[j].y = fmaf(xv, w2.y, av[j].y);
            av[j].z = fmaf(xv, w2.z, av[j].z);
            av[j].w = fmaf(xv, w2.w, av[j].w);
        }
    }

    float4 bmv = *reinterpret_cast<const float4*>(&bm[dq]);
    float4 bsv = *reinterpret_cast<const float4*>(&bs[dq]);
#pragma unroll
    for (int j = 0; j < 4; ++j) {
        int node = nbase + g * 4 + j;
        if (node < NN) {
            float4 a = am[j], v = av[j];
            a.x += bmv.x; a.y += bmv.y; a.z += bmv.z; a.w += bmv.w;
            v.x += bsv.x; v.y += bsv.y; v.z += bsv.z; v.w += bsv.w;
            const int o = node * D + dq;
            *reinterpret_cast<float4*>(&g_msgs[o]) = a;
            *reinterpret_cast<float4*>(&out[o])    = v;
        }
    }
}

// ---------------------------------------------------------------------------
// Grid scan, now 2 kernels (scan2 folded into scan3).
// ---------------------------------------------------------------------------
__device__ __forceinline__ int warp_incl_scan(int v, int lane) {
#pragma unroll
    for (int off = 1; off < 32; off <<= 1) {
        int n = __shfl_up_sync(0xFFFFFFFFu, v, off);
        if (lane >= off) v += n;
    }
    return v;
}

// scan1: per-block exclusive scan of counts (READ-ONLY on g_counts — pos
// drains them to zero later). Writes block-local prefixes + block sums.
__global__ __launch_bounds__(256) void scan1_kernel() {
    __shared__ int wsum[8];
    const int t = threadIdx.x;
    const int lane = t & 31;
    const int w = t >> 5;
    const int idx = blockIdx.x * 256 + t;

    int v = (idx < NN) ? g_counts[idx] : 0;
    int inc = warp_incl_scan(v, lane);
    if (lane == 31) wsum[w] = inc;
    __syncthreads();

    if (w == 0) {
        int s = (lane < 8) ? wsum[lane] : 0;
        int si = warp_incl_scan(s, lane);
        if (lane < 8) wsum[lane] = si - s;   // exclusive warp offsets
        if (lane == 7) g_bsums[blockIdx.x] = si;
    }
    __syncthreads();

    if (idx < NN) g_offsets[idx] = inc - v + wsum[w];   // block-local exclusive
}

// scan3: each block recomputes the bsums prefix itself (196 = 28 lanes x 7,
// one L2 round-trip, all loads independent) -> the scan2 launch is gone.
__global__ __launch_bounds__(256) void scan3_kernel() {
    __shared__ int blk_off;
    const int t = threadIdx.x;

    if (t < 32) {   // warp 0: exclusive prefix of block sums up to blockIdx.x
        const int lane = t;
        const int base = lane * 7;
        int v[7];
#pragma unroll
        for (int i = 0; i < 7; ++i) {
            int gidx = base + i;
            v[i] = (lane < 28 && gidx < SCAN_BLOCKS) ? g_bsums[gidx] : 0;
        }
        int s = 0;
#pragma unroll
        for (int i = 0; i < 7; ++i) s += v[i];
        int run = warp_incl_scan(s, lane) - s;   // exclusive prefix of lane chunk
        // locate blockIdx.x inside this lane's chunk
        int want = blockIdx.x;
        int my = -1;
#pragma unroll
        for (int i = 0; i < 7; ++i) {
            if (base + i == want) my = run;
            run += v[i];
        }
        // exactly one lane found it; reduce via max (my>=0 there, -1 elsewhere)
#pragma unroll
        for (int off = 16; off > 0; off >>= 1)
            my = max(my, __shfl_xor_sync(0xFFFFFFFFu, my, off));
        if (lane == 0) blk_off = my;
    }
    __syncthreads();

    const int idx = blockIdx.x * 256 + t;
    if (idx < NN) g_offsets[idx] += blk_off;
    if (blockIdx.x == 0 && t == 0) g_offsets[NN] = NE;  // all (clamped) edges counted
}

// ---------------------------------------------------------------------------
// Position scatter, countdown form: g_counts[c] holds deg after the
// histogram; each edge claims slot offsets[c] + (--count). Slots fill in
// reverse (any within-segment order is valid) and g_counts DRAINS TO ZERO,
// making it replay-ready without any reset pass.
// ---------------------------------------------------------------------------
__global__ __launch_bounds__(256) void pos_kernel(const int* __restrict__ ei) {
    int e = blockIdx.x * 256 + threadIdx.x;
    if (e < NE) {
        int r = __ldg(&ei[e]);
        int c = __ldg(&ei[NE + e]);
        r = min(max(r, 0), NN - 1);
        c = min(max(c, 0), NN - 1);
        int p = __ldg(&g_offsets[c]) + atomicAdd(&g_counts[c], -1) - 1;
        g_srcs[p] = r;
    }
}

// ---------------------------------------------------------------------------
// Warp-per-node gather + mean + self-add. ZERO atomics.
// Lane l owns dims {2l, 2l+1} via float2 (LDG.64). 4x edge unroll (avg deg
// 16). At the L2-read roofline (~205MB / 6300 B/cyc).
// ---------------------------------------------------------------------------
__global__ __launch_bounds__(256) void aggregate_kernel(float* __restrict__ out) {
    const int node = blockIdx.x * 8 + (threadIdx.x >> 5);
    if (node >= NN) return;
    const int lane = threadIdx.x & 31;

    const int start = __ldg(&g_offsets[node]);
    const int end   = __ldg(&g_offsets[node + 1]);

    const float2* __restrict__ msgs2 = reinterpret_cast<const float2*>(g_msgs);

    float ax = 0.f, ay = 0.f;
    int j = start;
    for (; j + 4 <= end; j += 4) {
        int s0 = __ldg(&g_srcs[j]);
        int s1 = __ldg(&g_srcs[j + 1]);
        int s2 = __ldg(&g_srcs[j + 2]);
        int s3 = __ldg(&g_srcs[j + 3]);
        float2 v0 = __ldg(&msgs2[s0 * 32 + lane]);
        float2 v1 = __ldg(&msgs2[s1 * 32 + lane]);
        float2 v2 = __ldg(&msgs2[s2 * 32 + lane]);
        float2 v3 = __ldg(&msgs2[s3 * 32 + lane]);
        ax += (v0.x + v1.x) + (v2.x + v3.x);
        ay += (v0.y + v1.y) + (v2.y + v3.y);
    }
    for (; j < end; ++j) {
        int s0 = __ldg(&g_srcs[j]);
        float2 v0 = __ldg(&msgs2[s0 * 32 + lane]);
        ax += v0.x;
        ay += v0.y;
    }

    const float inv = 1.0f / fmaxf((float)(end - start), 1.0f);
    float2* out2 = reinterpret_cast<float2*>(out);
    float2 o = out2[node * 32 + lane];
    o.x = fmaf(ax, inv, o.x);
    o.y = fmaf(ay, inv, o.y);
    out2[node * 32 + lane] = o;
}

// ---------------------------------------------------------------------------
// Serial single-stream launch: 5 launches (was 6 — scan2 folded into scan3).
// ---------------------------------------------------------------------------
extern "C" void kernel_launch(void* const* d_in, const int* in_sizes, int n_in,
                              void* d_out, int out_size)
{
    const float* x   = (const float*)d_in[0];
    const int*   ei  = (const int*)d_in[1];    // int32 (JAX x64-disabled)
    const float* Wm  = (const float*)d_in[2];
    const float* bm  = (const float*)d_in[3];
    const float* Ws  = (const float*)d_in[4];
    const float* bs  = (const float*)d_in[5];
    float*       out = (float*)d_out;

    (void)in_sizes; (void)n_in; (void)out_size;

    // 1) dual GEMM (scalar FFMA, roofline) + fused degree histogram
    dual_gemm_kernel<<<GEMM_BLOCKS, 256>>>(x, Wm, bm, Ws, bs, ei, out);

    // 2) scan: block-local prefixes, then per-block global fixup
    scan1_kernel<<<SCAN_BLOCKS, 256>>>();
    scan3_kernel<<<SCAN_BLOCKS, 256>>>();

    // 3) position scatter (countdown; drains g_counts to zero for replay)
    pos_kernel<<<(NE + 255) / 256, 256>>>(ei);

    // 4) gather + mean + self-add (atomic-free)
    aggregate_kernel<<<(NN + 7) / 8, 256>>>(out);
}